// round 16
// baseline (speedup 1.0000x reference)
#include <cuda_runtime.h>
#include <cuda_fp16.h>
#include <cstdint>

#define D_MODEL   1024
#define NUM_HEADS 16
#define D_HEAD    64
#define BATCH     2
#define SEQ       2048
#define ROWS      (BATCH * SEQ)   // 4096

// ---------------------------------------------------------------------------
// Scratch (alloc-free rule: __device__ globals)
// ---------------------------------------------------------------------------
__device__ __half g_qkvf[(size_t)ROWS * 3 * D_MODEL];    // qkv fp16
__device__ __half g_xf[(size_t)ROWS * D_MODEL];          // x as fp16
__device__ __half g_w1f[(size_t)3 * D_MODEL * D_MODEL];  // Wqkv fp16 (Q rows scaled)
__device__ __half g_w2f[(size_t)D_MODEL * D_MODEL];      // Wout fp16
__device__ __half g_yf[(size_t)ROWS * D_MODEL];          // attention out, fp16

// ---------------------------------------------------------------------------
__device__ __forceinline__ uint32_t smem_u32(const void* p) {
    uint32_t a;
    asm("{ .reg .u64 t; cvta.to.shared.u64 t, %1; cvt.u32.u64 %0, t; }"
        : "=r"(a) : "l"(p));
    return a;
}

__device__ __forceinline__ void cp_async16(uint32_t dst, const void* src) {
    asm volatile("cp.async.cg.shared.global [%0], [%1], 16;" :: "r"(dst), "l"(src));
}

// fp16 MMA
__device__ __forceinline__ void mma16816h(float* c, const uint32_t* a, const uint32_t* b) {
    asm volatile(
        "mma.sync.aligned.m16n8k16.row.col.f32.f16.f16.f32 "
        "{%0,%1,%2,%3}, {%4,%5,%6,%7}, {%8,%9}, {%0,%1,%2,%3};"
        : "+f"(c[0]), "+f"(c[1]), "+f"(c[2]), "+f"(c[3])
        : "r"(a[0]), "r"(a[1]), "r"(a[2]), "r"(a[3]), "r"(b[0]), "r"(b[1]));
}

__device__ __forceinline__ void ldsm_x4(uint32_t* r, uint32_t addr) {
    asm volatile("ldmatrix.sync.aligned.m8n8.x4.shared.b16 {%0,%1,%2,%3}, [%4];"
        : "=r"(r[0]), "=r"(r[1]), "=r"(r[2]), "=r"(r[3]) : "r"(addr));
}

__device__ __forceinline__ void ldsm_x4_t(uint32_t* r, uint32_t addr) {
    asm volatile("ldmatrix.sync.aligned.m8n8.x4.trans.shared.b16 {%0,%1,%2,%3}, [%4];"
        : "=r"(r[0]), "=r"(r[1]), "=r"(r[2]), "=r"(r[3]) : "r"(addr));
}

__device__ __forceinline__ uint32_t pack_f16x2(float x, float y) {
    uint32_t r;
    asm("cvt.rn.f16x2.f32 %0, %1, %2;" : "=r"(r) : "f"(y), "f"(x));
    return r;
}

// ---------------------------------------------------------------------------
// Fused fp32 -> fp16 convert over x | Wqkv | Wout (one launch).
// Wqkv Q-rows (first third of w1) scaled by qscale.
// ---------------------------------------------------------------------------
#define XN4   (ROWS * D_MODEL / 4)
#define W1N4  (3 * D_MODEL * D_MODEL / 4)
#define W2N4  (D_MODEL * D_MODEL / 4)

__global__ __launch_bounds__(256) void conv_all(const float* __restrict__ x,
                                                const float* __restrict__ w1,
                                                const float* __restrict__ w2,
                                                __half* __restrict__ xf,
                                                __half* __restrict__ w1f,
                                                __half* __restrict__ w2f,
                                                float qscale) {
    int i = blockIdx.x * blockDim.x + threadIdx.x;
    const float* src;
    __half* dst;
    float s = 1.0f;
    if (i < XN4) {
        src = x; dst = xf;
    } else if (i < XN4 + W1N4) {
        i -= XN4;
        src = w1; dst = w1f;
        if (i < W1N4 / 3) s = qscale;   // Q rows of Wqkv
    } else {
        i -= XN4 + W1N4;
        if (i >= W2N4) return;
        src = w2; dst = w2f;
    }
    float4 v = ((const float4*)src)[i];
    uint32_t p0 = pack_f16x2(v.x * s, v.y * s);
    uint32_t p1 = pack_f16x2(v.z * s, v.w * s);
    ((uint2*)dst)[i] = make_uint2(p0, p1);
}

// ---------------------------------------------------------------------------
// fp16 GEMM NT: C[m,n] = sum_k A[m,k]*B[n,k]
// Block 128x128, BK=32, 8 warps (warp 64x32), 4-stage cp.async, 2 CTAs/SM.
// Single barrier per iter: wait(2) -> sync -> prefetch(it+3) -> commit -> compute.
// ---------------------------------------------------------------------------
#define SROW       40                    // fp16 elems per smem row (80 B)
#define TILE_B     (128 * SROW * 2)      // 10240 B per tile
#define STAGE_B    (2 * TILE_B)          // A, B = 20480 B
#define NSTAGE     4
#define GEMM_SMEM  (NSTAGE * STAGE_B)    // 81920 B

__device__ __forceinline__ void load_stage(uint32_t s_base,
                                           const __half* Af, const __half* Bf,
                                           int m0, int n0, int k0, int K, int tid) {
#pragma unroll
    for (int p = 0; p < 2; p++) {
        int v = tid + p * 256;           // 0..511
        int row = v >> 2;                // 0..127
        int c = v & 3;                   // 0..3 (16B chunks of the 64B row)
        uint32_t soff = (uint32_t)(row * (SROW * 2) + c * 16);
        cp_async16(s_base + soff,
                   Af + (size_t)(m0 + row) * K + k0 + c * 8);
        cp_async16(s_base + TILE_B + soff,
                   Bf + (size_t)(n0 + row) * K + k0 + c * 8);
    }
}

template <bool F16OUT>
__global__ __launch_bounds__(256, 2) void gemm_f16(const __half* __restrict__ Af,
                                                   const __half* __restrict__ Bf,
                                                   float* __restrict__ C,
                                                   __half* __restrict__ Cf,
                                                   int M, int N, int K) {
    extern __shared__ __half smem[];
    const uint32_t sbase = smem_u32(smem);

    const int tid = threadIdx.x;
    const int wid = tid >> 5;
    const int lane = tid & 31;
    const int g = lane >> 2;
    const int t = lane & 3;
    const int m0 = blockIdx.y * 128;
    const int n0 = blockIdx.x * 128;
    const int wm = (wid >> 2) * 64;
    const int wn = (wid & 3) * 32;

    const int lrow  = (lane & 7) + 8 * ((lane >> 3) & 1);   // A frag
    const int lcol8 = 8 * (lane >> 4);
    const int lrowK = (lane & 7) + 8 * (lane >> 4);          // B frag
    const int lcol8K = 8 * ((lane >> 3) & 1);

    float acc[4][4][4];
#pragma unroll
    for (int mi = 0; mi < 4; mi++)
#pragma unroll
        for (int ni = 0; ni < 4; ni++)
#pragma unroll
            for (int r = 0; r < 4; r++) acc[mi][ni][r] = 0.f;

    const int NIT = K / 32;   // 32

    // Prologue: stages 0..2
#pragma unroll
    for (int s = 0; s < NSTAGE - 1; s++) {
        load_stage(sbase + s * STAGE_B, Af, Bf, m0, n0, s * 32, K, tid);
        asm volatile("cp.async.commit_group;" ::: "memory");
    }

    for (int it = 0; it < NIT; it++) {
        // own copies for stage it complete (stages it+1, it+2 may be in flight)
        asm volatile("cp.async.wait_group 2;" ::: "memory");
        // cross-thread visibility + compute(it-1) done everywhere
        __syncthreads();
        // prefetch stage it+3 into slot (it-1)%4 — safe after the barrier
        if (it + NSTAGE - 1 < NIT) {
            load_stage(sbase + ((it + NSTAGE - 1) % NSTAGE) * STAGE_B, Af, Bf,
                       m0, n0, (it + NSTAGE - 1) * 32, K, tid);
        }
        asm volatile("cp.async.commit_group;" ::: "memory");

        const uint32_t sA = sbase + (it % NSTAGE) * STAGE_B;
        const uint32_t sB = sA + TILE_B;

#pragma unroll
        for (int ks = 0; ks < 2; ks++) {
            const int kb = ks * 16;
            uint32_t a[4][4], b[2][4];
#pragma unroll
            for (int np = 0; np < 2; np++) {
                uint32_t boff = (uint32_t)((wn + np * 16 + lrowK) * (SROW * 2)
                                           + (kb + lcol8K) * 2);
                ldsm_x4(b[np], sB + boff);
            }
#pragma unroll
            for (int mi = 0; mi < 4; mi++) {
                uint32_t aoff = (uint32_t)((wm + mi * 16 + lrow) * (SROW * 2)
                                           + (kb + lcol8) * 2);
                ldsm_x4(a[mi], sA + aoff);
            }
#pragma unroll
            for (int mi = 0; mi < 4; mi++)
#pragma unroll
                for (int np = 0; np < 2; np++) {
                    mma16816h(acc[mi][2 * np],     a[mi], b[np]);
                    mma16816h(acc[mi][2 * np + 1], a[mi], b[np] + 2);
                }
        }
    }

#pragma unroll
    for (int mi = 0; mi < 4; mi++) {
        int row0 = m0 + wm + mi * 16 + g;
#pragma unroll
        for (int ni = 0; ni < 4; ni++) {
            int col = n0 + wn + ni * 8 + 2 * t;
            if (F16OUT) {
                *(uint32_t*)&Cf[(size_t)row0 * N + col] =
                    pack_f16x2(acc[mi][ni][0], acc[mi][ni][1]);
                *(uint32_t*)&Cf[(size_t)(row0 + 8) * N + col] =
                    pack_f16x2(acc[mi][ni][2], acc[mi][ni][3]);
            } else {
                *(float2*)&C[(size_t)row0 * N + col] =
                    make_float2(acc[mi][ni][0], acc[mi][ni][1]);
                *(float2*)&C[(size_t)(row0 + 8) * N + col] =
                    make_float2(acc[mi][ni][2], acc[mi][ni][3]);
            }
        }
    }
}

// ---------------------------------------------------------------------------
// fp16 tensor-core causal flash attention. BQ=128, BK=64, Dh=64, 256 threads.
// Q, K, V single fp16. Q pre-scaled by 0.125*log2(e) -> softmax in exp2 domain.
// K/V FIVE-stage cp.async, single barrier per iter:
//   wait_group(3) -> sync -> prefetch(kt+4) -> commit -> compute(kt)
// LPT scheduling. smem: Q 18432 | 5 stages x 18432 = 110592 B (2 CTAs/SM)
// ---------------------------------------------------------------------------
#define AT_STAGE 18432
#define AT_NST   5
#define AT_SMEM  (18432 + AT_NST * AT_STAGE)   // 110592

__device__ __forceinline__ void load_kv(uint32_t stage_base,
                                        const __half* kf, const __half* vf,
                                        int k0, int tid) {
#pragma unroll
    for (int p = 0; p < 2; p++) {
        int v = tid + p * 256;        // 0..511
        int row = v >> 3, c = v & 7;
        size_t go = (size_t)(k0 + row) * (3 * D_MODEL) + c * 8;
        uint32_t soff = (uint32_t)(row * 144 + c * 16);
        cp_async16(stage_base + soff,        kf + go);
        cp_async16(stage_base + 9216 + soff, vf + go);
    }
}

__global__ __launch_bounds__(256, 2) void attn_tc(const __half* __restrict__ qkvf,
                                                  __half* __restrict__ yf) {
    extern __shared__ __half asmem[];
    const uint32_t sb = smem_u32(asmem);
    const uint32_t QS = sb;
    const uint32_t ST0 = sb + 18432;

    const int tid = threadIdx.x;
    const int wid = tid >> 5;
    const int lane = tid & 31;
    const int g = lane >> 2, t = lane & 3;
    // LPT: heaviest q-tiles (largest qt) scheduled first
    const int qt = (gridDim.x - 1) - blockIdx.x;
    const int h = blockIdx.y, b = blockIdx.z;
    const int q0 = qt * 128;

    const size_t rowstride = 3 * D_MODEL;
    const __half* qf = qkvf + (size_t)b * SEQ * rowstride + h * D_HEAD;
    const __half* kf = qf + D_MODEL;
    const __half* vf = qf + 2 * D_MODEL;

    const int lrow  = (lane & 7) + 8 * ((lane >> 3) & 1);
    const int lcol8 = 8 * (lane >> 4);
    const int lrowK = (lane & 7) + 8 * (lane >> 4);
    const int lcol8K = 8 * ((lane >> 3) & 1);

    // ---- async-load Q tile (group 0; retires before all KV groups) ----
#pragma unroll
    for (int p = 0; p < 4; p++) {
        int v = tid + p * 256;
        int row = v >> 3, c = v & 7;
        cp_async16(QS + row * 144 + c * 16,
                   qf + (size_t)(q0 + row) * rowstride + c * 8);
    }
    asm volatile("cp.async.commit_group;" ::: "memory");

    const int ntiles = 2 * qt + 2;
    // Prologue: stages 0..3 (always commit to keep group accounting uniform)
#pragma unroll
    for (int s = 0; s < AT_NST - 1; s++) {
        if (s < ntiles) load_kv(ST0 + s * AT_STAGE, kf, vf, s * 64, tid);
        asm volatile("cp.async.commit_group;" ::: "memory");
    }

    float m_[2] = {-1e30f, -1e30f};
    float l_[2] = {0.f, 0.f};
    float o[8][4];
#pragma unroll
    for (int nt = 0; nt < 8; nt++)
#pragma unroll
        for (int c = 0; c < 4; c++) o[nt][c] = 0.f;

    for (int kt = 0; kt < ntiles; kt++) {
        const uint32_t CUR = ST0 + (kt % AT_NST) * AT_STAGE;
        // own copies for stage kt (and Q) complete; kt+1..kt+3 may be in flight
        asm volatile("cp.async.wait_group 3;" ::: "memory");
        // cross-thread visibility + compute(kt-1) done everywhere
        __syncthreads();
        // prefetch stage kt+4 into slot (kt-1)%5 — safe after the barrier
        if (kt + AT_NST - 1 < ntiles) {
            load_kv(ST0 + ((kt + AT_NST - 1) % AT_NST) * AT_STAGE, kf, vf,
                    (kt + AT_NST - 1) * 64, tid);
        }
        asm volatile("cp.async.commit_group;" ::: "memory");

        const uint32_t KS = CUR, VS = CUR + 9216;

        // ---- S = Q K^T (log2-domain scores) ----
        float s[8][4];
#pragma unroll
        for (int nt = 0; nt < 8; nt++)
#pragma unroll
            for (int c = 0; c < 4; c++) s[nt][c] = 0.f;

#pragma unroll
        for (int ks = 0; ks < 4; ks++) {
            uint32_t a[4];
            uint32_t qoff = (uint32_t)((wid * 16 + lrow) * 144 + (ks * 16 + lcol8) * 2);
            ldsm_x4(a, QS + qoff);
#pragma unroll
            for (int ntp = 0; ntp < 4; ntp++) {
                uint32_t bk[4];
                uint32_t koff = (uint32_t)((ntp * 16 + lrowK) * 144 + (ks * 16 + lcol8K) * 2);
                ldsm_x4(bk, KS + koff);
                mma16816h(s[2 * ntp],     a, bk);
                mma16816h(s[2 * ntp + 1], a, bk + 2);
            }
        }

        // ---- causal mask ----
        if (kt >= 2 * qt) {
#pragma unroll
            for (int nt = 0; nt < 8; nt++)
#pragma unroll
                for (int c = 0; c < 4; c++) {
                    int row = q0 + wid * 16 + g + (c >> 1) * 8;
                    int col = kt * 64 + nt * 8 + 2 * t + (c & 1);
                    if (col > row) s[nt][c] = -1e30f;
                }
        }

        // ---- online softmax (exp2 domain) ----
#pragma unroll
        for (int r = 0; r < 2; r++) {
            float mx = -1e30f;
#pragma unroll
            for (int nt = 0; nt < 8; nt++)
                mx = fmaxf(mx, fmaxf(s[nt][2 * r], s[nt][2 * r + 1]));
            mx = fmaxf(mx, __shfl_xor_sync(0xffffffffu, mx, 1));
            mx = fmaxf(mx, __shfl_xor_sync(0xffffffffu, mx, 2));
            float mnew = fmaxf(m_[r], mx);
            float corr = exp2f(m_[r] - mnew);
            m_[r] = mnew;
            float ls = 0.f;
#pragma unroll
            for (int nt = 0; nt < 8; nt++) {
                float p0 = exp2f(s[nt][2 * r] - mnew);
                float p1 = exp2f(s[nt][2 * r + 1] - mnew);
                s[nt][2 * r] = p0;
                s[nt][2 * r + 1] = p1;
                ls += p0 + p1;
            }
            ls += __shfl_xor_sync(0xffffffffu, ls, 1);
            ls += __shfl_xor_sync(0xffffffffu, ls, 2);
            l_[r] = l_[r] * corr + ls;
#pragma unroll
            for (int nt = 0; nt < 8; nt++) {
                o[nt][2 * r] *= corr;
                o[nt][2 * r + 1] *= corr;
            }
        }

        // ---- O += f16(P) V ----
#pragma unroll
        for (int kc = 0; kc < 4; kc++) {
            uint32_t pa[4];
            pa[0] = pack_f16x2(s[2 * kc][0],     s[2 * kc][1]);
            pa[1] = pack_f16x2(s[2 * kc][2],     s[2 * kc][3]);
            pa[2] = pack_f16x2(s[2 * kc + 1][0], s[2 * kc + 1][1]);
            pa[3] = pack_f16x2(s[2 * kc + 1][2], s[2 * kc + 1][3]);
#pragma unroll
            for (int ntp = 0; ntp < 4; ntp++) {
                uint32_t bv[4];
                uint32_t voff = (uint32_t)((kc * 16 + lrow) * 144 + (ntp * 16 + lcol8) * 2);
                ldsm_x4_t(bv, VS + voff);
                mma16816h(o[2 * ntp],     pa, bv);
                mma16816h(o[2 * ntp + 1], pa, bv + 2);
            }
        }
    }

    // ---- epilogue: normalize + write y as fp16 ----
    {
        float inv0 = 1.f / l_[0];
        float inv1 = 1.f / l_[1];
        int row0 = q0 + wid * 16 + g;
        size_t t0 = (size_t)b * SEQ + row0;
#pragma unroll
        for (int nt = 0; nt < 8; nt++) {
            int col = h * D_HEAD + nt * 8 + 2 * t;
            *(uint32_t*)&yf[t0 * D_MODEL + col] =
                pack_f16x2(o[nt][0] * inv0, o[nt][1] * inv0);
            *(uint32_t*)&yf[(t0 + 8) * D_MODEL + col] =
                pack_f16x2(o[nt][2] * inv1, o[nt][3] * inv1);
        }
    }
}

// ---------------------------------------------------------------------------
extern "C" void kernel_launch(void* const* d_in, const int* in_sizes, int n_in,
                              void* d_out, int out_size) {
    const float* x    = (const float*)d_in[0];
    const float* Wqkv = (const float*)d_in[1];
    const float* Wout = (const float*)d_in[2];
    float* out = (float*)d_out;

    __half *qkvf, *xf, *w1f, *w2f, *yf;
    cudaGetSymbolAddress((void**)&qkvf, g_qkvf);
    cudaGetSymbolAddress((void**)&xf, g_xf);
    cudaGetSymbolAddress((void**)&w1f, g_w1f);
    cudaGetSymbolAddress((void**)&w2f, g_w2f);
    cudaGetSymbolAddress((void**)&yf, g_yf);

    cudaFuncSetAttribute(gemm_f16<true>, cudaFuncAttributeMaxDynamicSharedMemorySize, GEMM_SMEM);
    cudaFuncSetAttribute(gemm_f16<false>, cudaFuncAttributeMaxDynamicSharedMemorySize, GEMM_SMEM);
    cudaFuncSetAttribute(attn_tc, cudaFuncAttributeMaxDynamicSharedMemorySize, AT_SMEM);

    // Fused converts. Wqkv Q-rows pre-scaled by (1/8)*log2(e).
    {
        const float QSCALE = 0.125f * 1.4426950408889634f;
        int total4 = XN4 + W1N4 + W2N4;
        conv_all<<<(total4 + 255) / 256, 256>>>(x, Wqkv, Wout, xf, w1f, w2f, QSCALE);
    }

    // 1) QKV projection -> fp16 qkv
    gemm_f16<true><<<dim3(3 * D_MODEL / 128, ROWS / 128), 256, GEMM_SMEM>>>(
        xf, w1f, nullptr, qkvf, ROWS, 3 * D_MODEL, D_MODEL);

    // 2) fp16 tensor-core causal flash attention (LPT order) -> yf
    attn_tc<<<dim3(SEQ / 128, NUM_HEADS, BATCH), 256, AT_SMEM>>>(qkvf, yf);

    // 3) Output projection -> fp32 out
    gemm_f16<false><<<dim3(D_MODEL / 128, ROWS / 128), 256, GEMM_SMEM>>>(
        yf, w2f, out, nullptr, ROWS, D_MODEL, D_MODEL);
}

// round 17
// speedup vs baseline: 1.0242x; 1.0242x over previous
#include <cuda_runtime.h>
#include <cuda_fp16.h>
#include <cstdint>

#define D_MODEL   1024
#define NUM_HEADS 16
#define D_HEAD    64
#define BATCH     2
#define SEQ       2048
#define ROWS      (BATCH * SEQ)   // 4096

// ---------------------------------------------------------------------------
// Scratch (alloc-free rule: __device__ globals)
// ---------------------------------------------------------------------------
__device__ __half g_qkvf[(size_t)ROWS * 3 * D_MODEL];    // qkv fp16
__device__ __half g_xf[(size_t)ROWS * D_MODEL];          // x as fp16
__device__ __half g_w1f[(size_t)3 * D_MODEL * D_MODEL];  // Wqkv fp16 (Q rows scaled)
__device__ __half g_w2f[(size_t)D_MODEL * D_MODEL];      // Wout fp16
__device__ __half g_yf[(size_t)ROWS * D_MODEL];          // attention out, fp16

// ---------------------------------------------------------------------------
__device__ __forceinline__ uint32_t smem_u32(const void* p) {
    uint32_t a;
    asm("{ .reg .u64 t; cvta.to.shared.u64 t, %1; cvt.u32.u64 %0, t; }"
        : "=r"(a) : "l"(p));
    return a;
}

__device__ __forceinline__ void cp_async16(uint32_t dst, const void* src) {
    asm volatile("cp.async.cg.shared.global [%0], [%1], 16;" :: "r"(dst), "l"(src));
}

// fp16 MMA
__device__ __forceinline__ void mma16816h(float* c, const uint32_t* a, const uint32_t* b) {
    asm volatile(
        "mma.sync.aligned.m16n8k16.row.col.f32.f16.f16.f32 "
        "{%0,%1,%2,%3}, {%4,%5,%6,%7}, {%8,%9}, {%0,%1,%2,%3};"
        : "+f"(c[0]), "+f"(c[1]), "+f"(c[2]), "+f"(c[3])
        : "r"(a[0]), "r"(a[1]), "r"(a[2]), "r"(a[3]), "r"(b[0]), "r"(b[1]));
}

__device__ __forceinline__ void ldsm_x4(uint32_t* r, uint32_t addr) {
    asm volatile("ldmatrix.sync.aligned.m8n8.x4.shared.b16 {%0,%1,%2,%3}, [%4];"
        : "=r"(r[0]), "=r"(r[1]), "=r"(r[2]), "=r"(r[3]) : "r"(addr));
}

__device__ __forceinline__ void ldsm_x4_t(uint32_t* r, uint32_t addr) {
    asm volatile("ldmatrix.sync.aligned.m8n8.x4.trans.shared.b16 {%0,%1,%2,%3}, [%4];"
        : "=r"(r[0]), "=r"(r[1]), "=r"(r[2]), "=r"(r[3]) : "r"(addr));
}

__device__ __forceinline__ uint32_t pack_f16x2(float x, float y) {
    uint32_t r;
    asm("cvt.rn.f16x2.f32 %0, %1, %2;" : "=r"(r) : "f"(y), "f"(x));
    return r;
}

// ---------------------------------------------------------------------------
// Fused fp32 -> fp16 convert over x | Wqkv | Wout (one launch).
// Wqkv Q-rows (first third of w1) scaled by qscale.
// ---------------------------------------------------------------------------
#define XN4   (ROWS * D_MODEL / 4)
#define W1N4  (3 * D_MODEL * D_MODEL / 4)
#define W2N4  (D_MODEL * D_MODEL / 4)

__global__ __launch_bounds__(256) void conv_all(const float* __restrict__ x,
                                                const float* __restrict__ w1,
                                                const float* __restrict__ w2,
                                                __half* __restrict__ xf,
                                                __half* __restrict__ w1f,
                                                __half* __restrict__ w2f,
                                                float qscale) {
    int i = blockIdx.x * blockDim.x + threadIdx.x;
    const float* src;
    __half* dst;
    float s = 1.0f;
    if (i < XN4) {
        src = x; dst = xf;
    } else if (i < XN4 + W1N4) {
        i -= XN4;
        src = w1; dst = w1f;
        if (i < W1N4 / 3) s = qscale;   // Q rows of Wqkv
    } else {
        i -= XN4 + W1N4;
        if (i >= W2N4) return;
        src = w2; dst = w2f;
    }
    float4 v = ((const float4*)src)[i];
    uint32_t p0 = pack_f16x2(v.x * s, v.y * s);
    uint32_t p1 = pack_f16x2(v.z * s, v.w * s);
    ((uint2*)dst)[i] = make_uint2(p0, p1);
}

// ---------------------------------------------------------------------------
// fp16 GEMM NT: C[m,n] = sum_k A[m,k]*B[n,k]
// Block 128x128, BK=64, 8 warps (warp 64x32), 3-stage cp.async, 2 CTAs/SM.
// R15-proven pipeline: prefetch -> commit -> wait(2) -> sync -> compute -> sync.
// ---------------------------------------------------------------------------
#define SROW       72                    // fp16 elems per smem row (144 B)
#define TILE_B     (128 * SROW * 2)      // 18432 B per tile
#define STAGE_B    (2 * TILE_B)          // A, B = 36864 B
#define NSTAGE     3
#define GEMM_SMEM  (NSTAGE * STAGE_B)    // 110592 B

__device__ __forceinline__ void load_stage(uint32_t s_base,
                                           const __half* Af, const __half* Bf,
                                           int m0, int n0, int k0, int K, int tid) {
#pragma unroll
    for (int p = 0; p < 4; p++) {
        int v = tid + p * 256;           // 0..1023
        int row = v >> 3;
        int c = v & 7;
        uint32_t soff = (uint32_t)(row * (SROW * 2) + c * 16);
        cp_async16(s_base + soff,
                   Af + (size_t)(m0 + row) * K + k0 + c * 8);
        cp_async16(s_base + TILE_B + soff,
                   Bf + (size_t)(n0 + row) * K + k0 + c * 8);
    }
}

template <bool F16OUT>
__global__ __launch_bounds__(256, 2) void gemm_f16(const __half* __restrict__ Af,
                                                   const __half* __restrict__ Bf,
                                                   float* __restrict__ C,
                                                   __half* __restrict__ Cf,
                                                   int M, int N, int K) {
    extern __shared__ __half smem[];
    const uint32_t sbase = smem_u32(smem);

    const int tid = threadIdx.x;
    const int wid = tid >> 5;
    const int lane = tid & 31;
    const int g = lane >> 2;
    const int t = lane & 3;
    const int m0 = blockIdx.y * 128;
    const int n0 = blockIdx.x * 128;
    const int wm = (wid >> 2) * 64;
    const int wn = (wid & 3) * 32;

    const int lrow  = (lane & 7) + 8 * ((lane >> 3) & 1);   // A frag
    const int lcol8 = 8 * (lane >> 4);
    const int lrowK = (lane & 7) + 8 * (lane >> 4);          // B frag
    const int lcol8K = 8 * ((lane >> 3) & 1);

    float acc[4][4][4];
#pragma unroll
    for (int mi = 0; mi < 4; mi++)
#pragma unroll
        for (int ni = 0; ni < 4; ni++)
#pragma unroll
            for (int r = 0; r < 4; r++) acc[mi][ni][r] = 0.f;

    const int NIT = K / 64;   // 16

    // Prologue: stages 0,1
#pragma unroll
    for (int s = 0; s < NSTAGE - 1; s++) {
        load_stage(sbase + s * STAGE_B, Af, Bf, m0, n0, s * 64, K, tid);
        asm volatile("cp.async.commit_group;" ::: "memory");
    }

    for (int it = 0; it < NIT; it++) {
        if (it + NSTAGE - 1 < NIT) {
            load_stage(sbase + ((it + NSTAGE - 1) % NSTAGE) * STAGE_B, Af, Bf,
                       m0, n0, (it + NSTAGE - 1) * 64, K, tid);
        }
        asm volatile("cp.async.commit_group;" ::: "memory");
        asm volatile("cp.async.wait_group %0;" :: "n"(NSTAGE - 1) : "memory");
        __syncthreads();

        const uint32_t sA = sbase + (it % NSTAGE) * STAGE_B;
        const uint32_t sB = sA + TILE_B;

#pragma unroll
        for (int ks = 0; ks < 4; ks++) {
            const int kb = ks * 16;
            uint32_t a[4][4], b[2][4];
#pragma unroll
            for (int np = 0; np < 2; np++) {
                uint32_t boff = (uint32_t)((wn + np * 16 + lrowK) * (SROW * 2)
                                           + (kb + lcol8K) * 2);
                ldsm_x4(b[np], sB + boff);
            }
#pragma unroll
            for (int mi = 0; mi < 4; mi++) {
                uint32_t aoff = (uint32_t)((wm + mi * 16 + lrow) * (SROW * 2)
                                           + (kb + lcol8) * 2);
                ldsm_x4(a[mi], sA + aoff);
            }
#pragma unroll
            for (int mi = 0; mi < 4; mi++)
#pragma unroll
                for (int np = 0; np < 2; np++) {
                    mma16816h(acc[mi][2 * np],     a[mi], b[np]);
                    mma16816h(acc[mi][2 * np + 1], a[mi], b[np] + 2);
                }
        }
        __syncthreads();
    }

#pragma unroll
    for (int mi = 0; mi < 4; mi++) {
        int row0 = m0 + wm + mi * 16 + g;
#pragma unroll
        for (int ni = 0; ni < 4; ni++) {
            int col = n0 + wn + ni * 8 + 2 * t;
            if (F16OUT) {
                *(uint32_t*)&Cf[(size_t)row0 * N + col] =
                    pack_f16x2(acc[mi][ni][0], acc[mi][ni][1]);
                *(uint32_t*)&Cf[(size_t)(row0 + 8) * N + col] =
                    pack_f16x2(acc[mi][ni][2], acc[mi][ni][3]);
            } else {
                *(float2*)&C[(size_t)row0 * N + col] =
                    make_float2(acc[mi][ni][0], acc[mi][ni][1]);
                *(float2*)&C[(size_t)(row0 + 8) * N + col] =
                    make_float2(acc[mi][ni][2], acc[mi][ni][3]);
            }
        }
    }
}

// ---------------------------------------------------------------------------
// fp16 tensor-core causal flash attention. BQ=128, BK=64, Dh=64, 256 threads.
// Q, K, V single fp16. Q pre-scaled by 0.125*log2(e) -> softmax in exp2 domain.
// Q FRAGMENTS HOISTED TO REGISTERS (kt-invariant) — no QS ldsm in the mainloop.
// K/V 4-stage cp.async, single barrier per iter:
//   wait_group(2) -> sync -> prefetch(kt+3) -> commit -> compute(kt)
// LPT scheduling. smem: Q 18432 | 4 stages x 18432 = 92160 B (2 CTAs/SM)
// ---------------------------------------------------------------------------
#define AT_STAGE 18432
#define AT_NST   4
#define AT_SMEM  (18432 + AT_NST * AT_STAGE)   // 92160

__device__ __forceinline__ void load_kv(uint32_t stage_base,
                                        const __half* kf, const __half* vf,
                                        int k0, int tid) {
#pragma unroll
    for (int p = 0; p < 2; p++) {
        int v = tid + p * 256;        // 0..511
        int row = v >> 3, c = v & 7;
        size_t go = (size_t)(k0 + row) * (3 * D_MODEL) + c * 8;
        uint32_t soff = (uint32_t)(row * 144 + c * 16);
        cp_async16(stage_base + soff,        kf + go);
        cp_async16(stage_base + 9216 + soff, vf + go);
    }
}

__global__ __launch_bounds__(256, 2) void attn_tc(const __half* __restrict__ qkvf,
                                                  __half* __restrict__ yf) {
    extern __shared__ __half asmem[];
    const uint32_t sb = smem_u32(asmem);
    const uint32_t QS = sb;
    const uint32_t ST0 = sb + 18432;

    const int tid = threadIdx.x;
    const int wid = tid >> 5;
    const int lane = tid & 31;
    const int g = lane >> 2, t = lane & 3;
    // LPT: heaviest q-tiles (largest qt) scheduled first
    const int qt = (gridDim.x - 1) - blockIdx.x;
    const int h = blockIdx.y, b = blockIdx.z;
    const int q0 = qt * 128;

    const size_t rowstride = 3 * D_MODEL;
    const __half* qf = qkvf + (size_t)b * SEQ * rowstride + h * D_HEAD;
    const __half* kf = qf + D_MODEL;
    const __half* vf = qf + 2 * D_MODEL;

    const int lrow  = (lane & 7) + 8 * ((lane >> 3) & 1);
    const int lcol8 = 8 * (lane >> 4);
    const int lrowK = (lane & 7) + 8 * (lane >> 4);
    const int lcol8K = 8 * ((lane >> 3) & 1);

    // ---- async-load Q tile (commit group 0) ----
#pragma unroll
    for (int p = 0; p < 4; p++) {
        int v = tid + p * 256;
        int row = v >> 3, c = v & 7;
        cp_async16(QS + row * 144 + c * 16,
                   qf + (size_t)(q0 + row) * rowstride + c * 8);
    }
    asm volatile("cp.async.commit_group;" ::: "memory");

    const int ntiles = 2 * qt + 2;
    // Prologue: KV stages 0..2 (always commit: uniform group accounting)
#pragma unroll
    for (int s = 0; s < AT_NST - 1; s++) {
        if (s < ntiles) load_kv(ST0 + s * AT_STAGE, kf, vf, s * 64, tid);
        asm volatile("cp.async.commit_group;" ::: "memory");
    }

    // ---- hoist Q fragments into registers (kt-invariant) ----
    uint32_t q[4][4];
    asm volatile("cp.async.wait_group 3;" ::: "memory");   // Q (group 0) complete
    __syncthreads();
#pragma unroll
    for (int ks = 0; ks < 4; ks++) {
        uint32_t qoff = (uint32_t)((wid * 16 + lrow) * 144 + (ks * 16 + lcol8) * 2);
        ldsm_x4(q[ks], QS + qoff);
    }

    float m_[2] = {-1e30f, -1e30f};
    float l_[2] = {0.f, 0.f};
    float o[8][4];
#pragma unroll
    for (int nt = 0; nt < 8; nt++)
#pragma unroll
        for (int c = 0; c < 4; c++) o[nt][c] = 0.f;

    for (int kt = 0; kt < ntiles; kt++) {
        const uint32_t CUR = ST0 + (kt % AT_NST) * AT_STAGE;
        // own copies for stage kt complete; kt+1, kt+2 may be in flight
        asm volatile("cp.async.wait_group 2;" ::: "memory");
        // cross-thread visibility + compute(kt-1) done everywhere
        __syncthreads();
        // prefetch stage kt+3 into slot (kt-1)%4 — safe after the barrier
        if (kt + AT_NST - 1 < ntiles) {
            load_kv(ST0 + ((kt + AT_NST - 1) % AT_NST) * AT_STAGE, kf, vf,
                    (kt + AT_NST - 1) * 64, tid);
        }
        asm volatile("cp.async.commit_group;" ::: "memory");

        const uint32_t KS = CUR, VS = CUR + 9216;

        // ---- S = Q K^T (log2-domain scores) ----
        float s[8][4];
#pragma unroll
        for (int nt = 0; nt < 8; nt++)
#pragma unroll
            for (int c = 0; c < 4; c++) s[nt][c] = 0.f;

#pragma unroll
        for (int ks = 0; ks < 4; ks++) {
#pragma unroll
            for (int ntp = 0; ntp < 4; ntp++) {
                uint32_t bk[4];
                uint32_t koff = (uint32_t)((ntp * 16 + lrowK) * 144 + (ks * 16 + lcol8K) * 2);
                ldsm_x4(bk, KS + koff);
                mma16816h(s[2 * ntp],     q[ks], bk);
                mma16816h(s[2 * ntp + 1], q[ks], bk + 2);
            }
        }

        // ---- causal mask ----
        if (kt >= 2 * qt) {
#pragma unroll
            for (int nt = 0; nt < 8; nt++)
#pragma unroll
                for (int c = 0; c < 4; c++) {
                    int row = q0 + wid * 16 + g + (c >> 1) * 8;
                    int col = kt * 64 + nt * 8 + 2 * t + (c & 1);
                    if (col > row) s[nt][c] = -1e30f;
                }
        }

        // ---- online softmax (exp2 domain) ----
#pragma unroll
        for (int r = 0; r < 2; r++) {
            float mx = -1e30f;
#pragma unroll
            for (int nt = 0; nt < 8; nt++)
                mx = fmaxf(mx, fmaxf(s[nt][2 * r], s[nt][2 * r + 1]));
            mx = fmaxf(mx, __shfl_xor_sync(0xffffffffu, mx, 1));
            mx = fmaxf(mx, __shfl_xor_sync(0xffffffffu, mx, 2));
            float mnew = fmaxf(m_[r], mx);
            float corr = exp2f(m_[r] - mnew);
            m_[r] = mnew;
            float ls = 0.f;
#pragma unroll
            for (int nt = 0; nt < 8; nt++) {
                float p0 = exp2f(s[nt][2 * r] - mnew);
                float p1 = exp2f(s[nt][2 * r + 1] - mnew);
                s[nt][2 * r] = p0;
                s[nt][2 * r + 1] = p1;
                ls += p0 + p1;
            }
            ls += __shfl_xor_sync(0xffffffffu, ls, 1);
            ls += __shfl_xor_sync(0xffffffffu, ls, 2);
            l_[r] = l_[r] * corr + ls;
#pragma unroll
            for (int nt = 0; nt < 8; nt++) {
                o[nt][2 * r] *= corr;
                o[nt][2 * r + 1] *= corr;
            }
        }

        // ---- O += f16(P) V ----
#pragma unroll
        for (int kc = 0; kc < 4; kc++) {
            uint32_t pa[4];
            pa[0] = pack_f16x2(s[2 * kc][0],     s[2 * kc][1]);
            pa[1] = pack_f16x2(s[2 * kc][2],     s[2 * kc][3]);
            pa[2] = pack_f16x2(s[2 * kc + 1][0], s[2 * kc + 1][1]);
            pa[3] = pack_f16x2(s[2 * kc + 1][2], s[2 * kc + 1][3]);
#pragma unroll
            for (int ntp = 0; ntp < 4; ntp++) {
                uint32_t bv[4];
                uint32_t voff = (uint32_t)((kc * 16 + lrow) * 144 + (ntp * 16 + lcol8) * 2);
                ldsm_x4_t(bv, VS + voff);
                mma16816h(o[2 * ntp],     pa, bv);
                mma16816h(o[2 * ntp + 1], pa, bv + 2);
            }
        }
    }

    // ---- epilogue: normalize + write y as fp16 ----
    {
        float inv0 = 1.f / l_[0];
        float inv1 = 1.f / l_[1];
        int row0 = q0 + wid * 16 + g;
        size_t t0 = (size_t)b * SEQ + row0;
#pragma unroll
        for (int nt = 0; nt < 8; nt++) {
            int col = h * D_HEAD + nt * 8 + 2 * t;
            *(uint32_t*)&yf[t0 * D_MODEL + col] =
                pack_f16x2(o[nt][0] * inv0, o[nt][1] * inv0);
            *(uint32_t*)&yf[(t0 + 8) * D_MODEL + col] =
                pack_f16x2(o[nt][2] * inv1, o[nt][3] * inv1);
        }
    }
}

// ---------------------------------------------------------------------------
extern "C" void kernel_launch(void* const* d_in, const int* in_sizes, int n_in,
                              void* d_out, int out_size) {
    const float* x    = (const float*)d_in[0];
    const float* Wqkv = (const float*)d_in[1];
    const float* Wout = (const float*)d_in[2];
    float* out = (float*)d_out;

    __half *qkvf, *xf, *w1f, *w2f, *yf;
    cudaGetSymbolAddress((void**)&qkvf, g_qkvf);
    cudaGetSymbolAddress((void**)&xf, g_xf);
    cudaGetSymbolAddress((void**)&w1f, g_w1f);
    cudaGetSymbolAddress((void**)&w2f, g_w2f);
    cudaGetSymbolAddress((void**)&yf, g_yf);

    cudaFuncSetAttribute(gemm_f16<true>, cudaFuncAttributeMaxDynamicSharedMemorySize, GEMM_SMEM);
    cudaFuncSetAttribute(gemm_f16<false>, cudaFuncAttributeMaxDynamicSharedMemorySize, GEMM_SMEM);
    cudaFuncSetAttribute(attn_tc, cudaFuncAttributeMaxDynamicSharedMemorySize, AT_SMEM);

    // Fused converts. Wqkv Q-rows pre-scaled by (1/8)*log2(e).
    {
        const float QSCALE = 0.125f * 1.4426950408889634f;
        int total4 = XN4 + W1N4 + W2N4;
        conv_all<<<(total4 + 255) / 256, 256>>>(x, Wqkv, Wout, xf, w1f, w2f, QSCALE);
    }

    // 1) QKV projection -> fp16 qkv
    gemm_f16<true><<<dim3(3 * D_MODEL / 128, ROWS / 128), 256, GEMM_SMEM>>>(
        xf, w1f, nullptr, qkvf, ROWS, 3 * D_MODEL, D_MODEL);

    // 2) fp16 tensor-core causal flash attention (LPT order) -> yf
    attn_tc<<<dim3(SEQ / 128, NUM_HEADS, BATCH), 256, AT_SMEM>>>(qkvf, yf);

    // 3) Output projection -> fp32 out
    gemm_f16<false><<<dim3(D_MODEL / 128, ROWS / 128), 256, GEMM_SMEM>>>(
        yf, w2f, out, nullptr, ROWS, D_MODEL, D_MODEL);
}